// round 15
// baseline (speedup 1.0000x reference)
#include <cuda_runtime.h>

// Shapes
// theta0: (256, 1024, 256)  idx = x0*262144 + j*256 + c
// theta1: (256, 256, 512)   idx = a*131072 + c*512 + j
// theta2: (256, 256, 512)   idx = c*131072 + b*512 + k
#define N0  67108864
#define N1  33554432
#define N2  33554432

// Scratch (device globals; fully rewritten every call -> deterministic)
__device__ float d_s0a[1024 * 256];      // sum over x0 of theta0  [j][c]
__device__ float d_S0p[2 * 256 * 512];   // partial sum over a of theta1 [half][c][j]
__device__ float d_S2[256 * 256];        // sum over j of theta1 [a][c]
__device__ float d_T2s[256 * 256];       // sum over k of theta2 [c][b]
__device__ float d_msg01[256 * 256];     // [a][c]
__device__ float d_msg12[256 * 256];     // [c][b]
__device__ float d_R[256 * 256];         // [c][b]  (msg21[c,j] = R[c, j>>1])
__device__ float d_Q[256 * 256];         // [a][c]  (msg10[j,c] = Q[j>>2, c])

// 256-bit loads (sm_103a: vector .v4.b64 form required for L2 hint qualifiers).
__device__ __forceinline__ void ldg_evict_last_8(const float* p, float* f) {
    unsigned long long a, b, c, d;
    asm volatile("ld.global.L2::evict_last.v4.b64 {%0,%1,%2,%3}, [%4];"
                 : "=l"(a), "=l"(b), "=l"(c), "=l"(d) : "l"(p));
    *(unsigned long long*)&f[0] = a;
    *(unsigned long long*)&f[2] = b;
    *(unsigned long long*)&f[4] = c;
    *(unsigned long long*)&f[6] = d;
}
__device__ __forceinline__ void ldg_evict_first_8(const float* p, float* f) {
    unsigned long long a, b, c, d;
    asm volatile("ld.global.L2::evict_first.v4.b64 {%0,%1,%2,%3}, [%4];"
                 : "=l"(a), "=l"(b), "=l"(c), "=l"(d) : "l"(p));
    *(unsigned long long*)&f[0] = a;
    *(unsigned long long*)&f[2] = b;
    *(unsigned long long*)&f[4] = c;
    *(unsigned long long*)&f[6] = d;
}

// ---------------------------------------------------------------------------
// KA: fused reductions. Block roles by blockIdx:
//   [0, 1024)     : k1  s0a[j][c] = sum_x0 theta0[x0,j,c]   (evict-first reads)
//   [1024, 1536)  : k2  dual reduction of theta1            (evict-first reads)
//   [1536, 9728)  : k3  T2s row sums of theta2              (evict_LAST reads)
// K3 is the grid tail -> t2 is the freshest protected data at KA's end;
// KB's out2 role consumes it from L2 immediately after the tiny K4.
__global__ void KA_reduce(const float* __restrict__ t0,
                          const float* __restrict__ t1,
                          const float* __restrict__ t2) {
    const unsigned bb = blockIdx.x;

    if (bb < 1024u) {
        // ---- k1 ----
        const int j = bb;
        const int c = threadIdx.x;
        const float* p = t0 + j * 256 + c;
        float a0 = 0.f, a1 = 0.f, a2 = 0.f, a3 = 0.f;
        float a4 = 0.f, a5 = 0.f, a6 = 0.f, a7 = 0.f;
        #pragma unroll 2
        for (int x = 0; x < 256; x += 8) {
            a0 += __ldcs(p + (size_t)(x + 0) * 262144);
            a1 += __ldcs(p + (size_t)(x + 1) * 262144);
            a2 += __ldcs(p + (size_t)(x + 2) * 262144);
            a3 += __ldcs(p + (size_t)(x + 3) * 262144);
            a4 += __ldcs(p + (size_t)(x + 4) * 262144);
            a5 += __ldcs(p + (size_t)(x + 5) * 262144);
            a6 += __ldcs(p + (size_t)(x + 6) * 262144);
            a7 += __ldcs(p + (size_t)(x + 7) * 262144);
        }
        d_s0a[j * 256 + c] = ((a0 + a1) + (a2 + a3)) + ((a4 + a5) + (a6 + a7));
        return;
    }

    if (bb < 1536u) {
        // ---- k2: dual reduction of theta1 (streaming 256-bit reads) ----
        const unsigned b2 = bb - 1024u;
        const int c    = b2 >> 1;
        const int half = b2 & 1;
        const int tid  = threadIdx.x;
        const int wid  = tid >> 5;
        const int lane = tid & 31;

        __shared__ float sS0[8][512];

        float acc[16];
        #pragma unroll
        for (int i = 0; i < 16; i++) acc[i] = 0.f;

        #pragma unroll 2
        for (int it = 0; it < 16; it++) {
            const int a = half * 128 + wid * 16 + it;
            const float* row = t1 + (size_t)a * 131072 + (size_t)c * 512;
            float rs = 0.f;
            #pragma unroll
            for (int g = 0; g < 2; g++) {
                float f[8];
                ldg_evict_first_8(row + (g * 32 + lane) * 8, f);
                #pragma unroll
                for (int e = 0; e < 8; e++) acc[g * 8 + e] += f[e];
                rs += ((f[0] + f[1]) + (f[2] + f[3])) + ((f[4] + f[5]) + (f[6] + f[7]));
            }
            #pragma unroll
            for (int off = 16; off > 0; off >>= 1)
                rs += __shfl_down_sync(0xffffffffu, rs, off);
            if (lane == 0) d_S2[a * 256 + c] = rs;
        }

        #pragma unroll
        for (int g = 0; g < 2; g++) {
            float4* dst = (float4*)&sS0[wid][(g * 32 + lane) * 8];
            dst[0] = make_float4(acc[g * 8 + 0], acc[g * 8 + 1], acc[g * 8 + 2], acc[g * 8 + 3]);
            dst[1] = make_float4(acc[g * 8 + 4], acc[g * 8 + 5], acc[g * 8 + 6], acc[g * 8 + 7]);
        }
        __syncthreads();

        float s0 = 0.f, s1 = 0.f;
        #pragma unroll
        for (int w = 0; w < 8; w++) {
            s0 += sS0[w][tid];
            s1 += sS0[w][tid + 256];
        }
        d_S0p[half * 131072 + c * 512 + tid]       = s0;
        d_S0p[half * 131072 + c * 512 + tid + 256] = s1;
        return;
    }

    // ---- k3: T2s[r] = sum_k theta2 row r (evict_last -> stays in L2 for KB) ----
    const int r    = (bb - 1536u) * 8 + (threadIdx.x >> 5);
    const int lane = threadIdx.x & 31;
    const float* row = t2 + (size_t)r * 512;
    float f[8];
    float s = 0.f;
    #pragma unroll
    for (int ch = 0; ch < 2; ch++) {
        ldg_evict_last_8(row + (ch * 32 + lane) * 8, f);
        s += ((f[0] + f[1]) + (f[2] + f[3])) + ((f[4] + f[5]) + (f[6] + f[7]));
    }
    #pragma unroll
    for (int off = 16; off > 0; off >>= 1)
        s += __shfl_down_sync(0xffffffffu, s, off);
    if (lane == 0) d_T2s[r] = s;
}

// ---------------------------------------------------------------------------
// K4: tiny message algebra. grid = 256 (c), block = 256.
__global__ void k4_messages() {
    const int c    = blockIdx.x;
    const int t    = threadIdx.x;
    const int lane = t & 31;
    const int wid  = t >> 5;
    __shared__ float sw[8];
    __shared__ float sbc;

    const float v0  = d_s0a[(4 * t + 0) * 256 + c];
    const float v1  = d_s0a[(4 * t + 1) * 256 + c];
    const float v2  = d_s0a[(4 * t + 2) * 256 + c];
    const float v3  = d_s0a[(4 * t + 3) * 256 + c];
    const float2 p0 = *(const float2*)&d_S0p[c * 512 + 2 * t];
    const float2 p1 = *(const float2*)&d_S0p[131072 + c * 512 + 2 * t];
    const float t2s = d_T2s[c * 256 + t];
    const float s2  = d_S2[t * 256 + c];

    const float m01 = (v0 + v1) + (v2 + v3);
    d_msg01[t * 256 + c] = m01;

    float r = m01;
    #pragma unroll
    for (int o = 16; o > 0; o >>= 1) r += __shfl_down_sync(0xffffffffu, r, o);
    if (lane == 0) sw[wid] = r;
    __syncthreads();
    if (t == 0) {
        float s = 0.f;
        #pragma unroll
        for (int w = 0; w < 8; w++) s += sw[w];
        sbc = s;
    }
    __syncthreads();
    const float colsum = sbc;

    const float m12 = (p0.x + p1.x + colsum) + (p0.y + p1.y + colsum);
    d_msg12[c * 256 + t] = m12;

    const float Rv = t2s + 511.f * m12;
    d_R[c * 256 + t] = Rv;

    r = Rv;
    #pragma unroll
    for (int o = 16; o > 0; o >>= 1) r += __shfl_down_sync(0xffffffffu, r, o);
    __syncthreads();
    if (lane == 0) sw[wid] = r;
    __syncthreads();
    if (t == 0) {
        float s = 0.f;
        #pragma unroll
        for (int w = 0; w < 8; w++) s += sw[w];
        sbc = 2.f * s;
    }
    __syncthreads();

    d_Q[t * 256 + c] = s2 + 511.f * m01 + sbc;
}

// ---------------------------------------------------------------------------
// KB: fused broadcast-add outputs, 256-bit loads (8 floats/thread).
//   [0, 16384)      : theta2 + msg12[c,b]   -- FIRST, reverse block order
//                     (t2 hot & protected in L2 from KA's k3; evict_first demotes)
//   [16384, 32768)  : theta1 + msg01[a,c] + R[c, j>>1]
//   [32768, 65536)  : theta0 + Q[j>>2, c]
__global__ void KB_outputs(const float* __restrict__ t0,
                           const float* __restrict__ t1,
                           const float* __restrict__ t2,
                           float* __restrict__ out) {
    const unsigned bb = blockIdx.x;
    float f[8];

    if (bb < 16384u) {
        // reverse order: read t2 tail first (freshest L2-resident lines)
        const int idx8 = (16383 - (int)bb) * 256 + threadIdx.x;
        const int i = idx8 << 3;
        const int r = i >> 9;                        // r = c*256 + b
        const float m = __ldg(&d_msg12[r]);
        ldg_evict_first_8(t2 + i, f);
        float* o = out + N0 + N1 + i;
        __stcs((float4*)o,     make_float4(f[0] + m, f[1] + m, f[2] + m, f[3] + m));
        __stcs((float4*)o + 1, make_float4(f[4] + m, f[5] + m, f[6] + m, f[7] + m));
        return;
    }

    if (bb < 32768u) {
        const int idx8 = ((int)bb - 16384) * 256 + threadIdx.x;
        const int i = idx8 << 3;
        const int j = i & 511;                       // 8-aligned
        const int c = (i >> 9) & 255;
        const int a = i >> 17;
        const float m = __ldg(&d_msg01[a * 256 + c]);
        const float4 rr = __ldg((const float4*)&d_R[c * 256 + (j >> 1)]);
        ldg_evict_first_8(t1 + i, f);
        float* o = out + N0 + i;
        __stcs((float4*)o,     make_float4(f[0] + m + rr.x, f[1] + m + rr.x,
                                           f[2] + m + rr.y, f[3] + m + rr.y));
        __stcs((float4*)o + 1, make_float4(f[4] + m + rr.z, f[5] + m + rr.z,
                                           f[6] + m + rr.w, f[7] + m + rr.w));
        return;
    }

    {
        const int idx8 = ((int)bb - 32768) * 256 + threadIdx.x;
        const int i = idx8 << 3;
        const int c = i & 255;                       // 8-aligned
        const int j = (i >> 8) & 1023;
        const float4 q0 = __ldg((const float4*)&d_Q[(j >> 2) * 256 + c]);
        const float4 q1 = __ldg((const float4*)&d_Q[(j >> 2) * 256 + c + 4]);
        ldg_evict_first_8(t0 + i, f);
        float* o = out + i;
        __stcs((float4*)o,     make_float4(f[0] + q0.x, f[1] + q0.y,
                                           f[2] + q0.z, f[3] + q0.w));
        __stcs((float4*)o + 1, make_float4(f[4] + q1.x, f[5] + q1.y,
                                           f[6] + q1.z, f[7] + q1.w));
    }
}

// ---------------------------------------------------------------------------
extern "C" void kernel_launch(void* const* d_in, const int* in_sizes, int n_in,
                              void* d_out, int out_size) {
    const float* t0 = (const float*)d_in[0];
    const float* t1 = (const float*)d_in[1];
    const float* t2 = (const float*)d_in[2];
    float* out = (float*)d_out;

    KA_reduce<<<9728, 256>>>(t0, t1, t2);
    k4_messages<<<256, 256>>>();
    KB_outputs<<<65536, 256>>>(t0, t1, t2, out);
}

// round 16
// speedup vs baseline: 1.0373x; 1.0373x over previous
#include <cuda_runtime.h>

// Shapes
// theta0: (256, 1024, 256)  idx = x0*262144 + j*256 + c
// theta1: (256, 256, 512)   idx = a*131072 + c*512 + j
// theta2: (256, 256, 512)   idx = c*131072 + b*512 + k
#define N0  67108864
#define N1  33554432
#define N2  33554432

// Scratch (device globals; fully rewritten every call -> deterministic)
__device__ float d_s0a[1024 * 256];      // sum over x0 of theta0  [j][c]
__device__ float d_S0p[2 * 256 * 512];   // partial sum over a of theta1 [half][c][j]
__device__ float d_S2[256 * 256];        // sum over j of theta1 [a][c]
__device__ float d_T2s[256 * 256];       // sum over k of theta2 [c][b]
__device__ float d_msg01[256 * 256];     // [a][c]
__device__ float d_msg12[256 * 256];     // [c][b]
__device__ float d_R[256 * 256];         // [c][b]  (msg21[c,j] = R[c, j>>1])
__device__ float d_Q[256 * 256];         // [a][c]  (msg10[j,c] = Q[j>>2, c])

// 256-bit evict_last load (sm_103a requires .v8.b32/.v4.b64 for this hint).
// Protects t2 lines in L2 across the KA->KB boundary (proven +22us in R10).
__device__ __forceinline__ void ldg_evict_last_8(const float* p, float* f) {
    unsigned long long a, b, c, d;
    asm volatile("ld.global.L2::evict_last.v4.b64 {%0,%1,%2,%3}, [%4];"
                 : "=l"(a), "=l"(b), "=l"(c), "=l"(d) : "l"(p));
    *(unsigned long long*)&f[0] = a;
    *(unsigned long long*)&f[2] = b;
    *(unsigned long long*)&f[4] = c;
    *(unsigned long long*)&f[6] = d;
}

// ---------------------------------------------------------------------------
// KA: fused reductions (exact R10 config). Block roles by blockIdx:
//   [0, 1024)     : k1  s0a[j][c] = sum_x0 theta0[x0,j,c]   (.cs reads)
//   [1024, 1536)  : k2  dual reduction of theta1            (.cs float4 reads)
//   [1536, 9728)  : k3  T2s row sums of theta2              (evict_LAST reads)
__global__ void KA_reduce(const float* __restrict__ t0,
                          const float* __restrict__ t1,
                          const float* __restrict__ t2) {
    const unsigned bb = blockIdx.x;

    if (bb < 1024u) {
        // ---- k1 ----
        const int j = bb;
        const int c = threadIdx.x;
        const float* p = t0 + j * 256 + c;
        float a0 = 0.f, a1 = 0.f, a2 = 0.f, a3 = 0.f;
        float a4 = 0.f, a5 = 0.f, a6 = 0.f, a7 = 0.f;
        #pragma unroll 2
        for (int x = 0; x < 256; x += 8) {
            a0 += __ldcs(p + (size_t)(x + 0) * 262144);
            a1 += __ldcs(p + (size_t)(x + 1) * 262144);
            a2 += __ldcs(p + (size_t)(x + 2) * 262144);
            a3 += __ldcs(p + (size_t)(x + 3) * 262144);
            a4 += __ldcs(p + (size_t)(x + 4) * 262144);
            a5 += __ldcs(p + (size_t)(x + 5) * 262144);
            a6 += __ldcs(p + (size_t)(x + 6) * 262144);
            a7 += __ldcs(p + (size_t)(x + 7) * 262144);
        }
        d_s0a[j * 256 + c] = ((a0 + a1) + (a2 + a3)) + ((a4 + a5) + (a6 + a7));
        return;
    }

    if (bb < 1536u) {
        // ---- k2: dual reduction of theta1 ----
        const unsigned b2 = bb - 1024u;
        const int c    = b2 >> 1;
        const int half = b2 & 1;
        const int tid  = threadIdx.x;
        const int wid  = tid >> 5;
        const int lane = tid & 31;

        __shared__ float4 sS0[8][128];

        float acc[16];
        #pragma unroll
        for (int i = 0; i < 16; i++) acc[i] = 0.f;

        #pragma unroll 2
        for (int it = 0; it < 16; it++) {
            const int a = half * 128 + wid * 16 + it;
            const float4* row = (const float4*)(t1 + (size_t)a * 131072 + (size_t)c * 512);
            float rs = 0.f;
            #pragma unroll
            for (int ch = 0; ch < 4; ch++) {
                float4 v = __ldcs(row + ch * 32 + lane);
                acc[ch * 4 + 0] += v.x;
                acc[ch * 4 + 1] += v.y;
                acc[ch * 4 + 2] += v.z;
                acc[ch * 4 + 3] += v.w;
                rs += (v.x + v.y) + (v.z + v.w);
            }
            #pragma unroll
            for (int off = 16; off > 0; off >>= 1)
                rs += __shfl_down_sync(0xffffffffu, rs, off);
            if (lane == 0) d_S2[a * 256 + c] = rs;
        }

        #pragma unroll
        for (int ch = 0; ch < 4; ch++)
            sS0[wid][ch * 32 + lane] = make_float4(acc[ch * 4 + 0], acc[ch * 4 + 1],
                                                   acc[ch * 4 + 2], acc[ch * 4 + 3]);
        __syncthreads();

        const float* sp = (const float*)sS0;
        float s0 = 0.f, s1 = 0.f;
        #pragma unroll
        for (int w = 0; w < 8; w++) {
            s0 += sp[w * 512 + tid];
            s1 += sp[w * 512 + tid + 256];
        }
        d_S0p[half * 131072 + c * 512 + tid]       = s0;
        d_S0p[half * 131072 + c * 512 + tid + 256] = s1;
        return;
    }

    // ---- k3: T2s[r] = sum_k theta2 row r (evict_last -> stays in L2 for KB) ----
    const int r    = (bb - 1536u) * 8 + (threadIdx.x >> 5);
    const int lane = threadIdx.x & 31;
    const float* row = t2 + (size_t)r * 512;
    float f[8];
    float s = 0.f;
    #pragma unroll
    for (int ch = 0; ch < 2; ch++) {
        ldg_evict_last_8(row + (ch * 32 + lane) * 8, f);
        s += ((f[0] + f[1]) + (f[2] + f[3])) + ((f[4] + f[5]) + (f[6] + f[7]));
    }
    #pragma unroll
    for (int off = 16; off > 0; off >>= 1)
        s += __shfl_down_sync(0xffffffffu, s, off);
    if (lane == 0) d_T2s[r] = s;
}

// ---------------------------------------------------------------------------
// K4: tiny message algebra (exact R10). grid = 256 (c), block = 256.
__global__ void k4_messages() {
    const int c    = blockIdx.x;
    const int t    = threadIdx.x;
    const int lane = t & 31;
    const int wid  = t >> 5;
    __shared__ float sw[8];
    __shared__ float sbc;

    const float v0  = d_s0a[(4 * t + 0) * 256 + c];
    const float v1  = d_s0a[(4 * t + 1) * 256 + c];
    const float v2  = d_s0a[(4 * t + 2) * 256 + c];
    const float v3  = d_s0a[(4 * t + 3) * 256 + c];
    const float2 p0 = *(const float2*)&d_S0p[c * 512 + 2 * t];
    const float2 p1 = *(const float2*)&d_S0p[131072 + c * 512 + 2 * t];
    const float t2s = d_T2s[c * 256 + t];
    const float s2  = d_S2[t * 256 + c];

    const float m01 = (v0 + v1) + (v2 + v3);
    d_msg01[t * 256 + c] = m01;

    float r = m01;
    #pragma unroll
    for (int o = 16; o > 0; o >>= 1) r += __shfl_down_sync(0xffffffffu, r, o);
    if (lane == 0) sw[wid] = r;
    __syncthreads();
    if (t == 0) {
        float s = 0.f;
        #pragma unroll
        for (int w = 0; w < 8; w++) s += sw[w];
        sbc = s;
    }
    __syncthreads();
    const float colsum = sbc;

    const float m12 = (p0.x + p1.x + colsum) + (p0.y + p1.y + colsum);
    d_msg12[c * 256 + t] = m12;

    const float Rv = t2s + 511.f * m12;
    d_R[c * 256 + t] = Rv;

    r = Rv;
    #pragma unroll
    for (int o = 16; o > 0; o >>= 1) r += __shfl_down_sync(0xffffffffu, r, o);
    __syncthreads();
    if (lane == 0) sw[wid] = r;
    __syncthreads();
    if (t == 0) {
        float s = 0.f;
        #pragma unroll
        for (int w = 0; w < 8; w++) s += sw[w];
        sbc = 2.f * s;
    }
    __syncthreads();

    d_Q[t * 256 + c] = s2 + 511.f * m01 + sbc;
}

// ---------------------------------------------------------------------------
// KB: fused broadcast-add outputs. ONLY delta vs R10: 2 independent float4
// per thread (MLP 2, both .cs loads issued before stores), 65536 blocks.
//   [0, 16384)      : theta2 + msg12[c,b]   -- FIRST, reverse order (L2 carry)
//   [16384, 32768)  : theta1 + msg01[a,c] + R[c, j>>1]
//   [32768, 65536)  : theta0 + Q[j>>2, c]
__global__ void KB_outputs(const float* __restrict__ t0,
                           const float* __restrict__ t1,
                           const float* __restrict__ t2,
                           float* __restrict__ out) {
    const unsigned bb = blockIdx.x;

    if (bb < 16384u) {
        // reverse order: read t2 tail first (freshest L2-resident lines)
        const int base4 = (16383 - (int)bb) * 512 + threadIdx.x;
        const int ia = base4;            // float4 index
        const int ib = base4 + 256;
        float4 va = __ldcs((const float4*)t2 + ia);
        float4 vb = __ldcs((const float4*)t2 + ib);
        const float ma = d_msg12[ia >> 7];      // r = (ia*4)>>9
        const float mb = d_msg12[ib >> 7];
        va.x += ma; va.y += ma; va.z += ma; va.w += ma;
        vb.x += mb; vb.y += mb; vb.z += mb; vb.w += mb;
        __stcs((float4*)(out + N0 + N1) + ia, va);
        __stcs((float4*)(out + N0 + N1) + ib, vb);
        return;
    }

    if (bb < 32768u) {
        const int base4 = ((int)bb - 16384) * 512 + threadIdx.x;
        const int ia = base4;
        const int ib = base4 + 256;
        float4 va = __ldcs((const float4*)t1 + ia);
        float4 vb = __ldcs((const float4*)t1 + ib);
        const int ea = ia << 2, eb = ib << 2;
        const int ja = ea & 511,            jb = eb & 511;
        const int ca = (ea >> 9) & 255,     cb = (eb >> 9) & 255;
        const int aa = ea >> 17,            ab = eb >> 17;
        const float m_a = d_msg01[aa * 256 + ca];
        const float m_b = d_msg01[ab * 256 + cb];
        const float2 ra = *(const float2*)&d_R[ca * 256 + (ja >> 1)];
        const float2 rb = *(const float2*)&d_R[cb * 256 + (jb >> 1)];
        va.x += m_a + ra.x; va.y += m_a + ra.x;
        va.z += m_a + ra.y; va.w += m_a + ra.y;
        vb.x += m_b + rb.x; vb.y += m_b + rb.x;
        vb.z += m_b + rb.y; vb.w += m_b + rb.y;
        __stcs((float4*)(out + N0) + ia, va);
        __stcs((float4*)(out + N0) + ib, vb);
        return;
    }

    {
        const int base4 = ((int)bb - 32768) * 512 + threadIdx.x;
        const int ia = base4;
        const int ib = base4 + 256;
        float4 va = __ldcs((const float4*)t0 + ia);
        float4 vb = __ldcs((const float4*)t0 + ib);
        const int ea = ia << 2, eb = ib << 2;
        const int ca = ea & 255,            cb = eb & 255;
        const int jpa = (ea >> 8) & 1023,   jpb = (eb >> 8) & 1023;
        float4 qa = ((const float4*)d_Q)[((jpa >> 2) << 6) + (ca >> 2)];
        float4 qb = ((const float4*)d_Q)[((jpb >> 2) << 6) + (cb >> 2)];
        va.x += qa.x; va.y += qa.y; va.z += qa.z; va.w += qa.w;
        vb.x += qb.x; vb.y += qb.y; vb.z += qb.z; vb.w += qb.w;
        __stcs((float4*)out + ia, va);
        __stcs((float4*)out + ib, vb);
    }
}

// ---------------------------------------------------------------------------
extern "C" void kernel_launch(void* const* d_in, const int* in_sizes, int n_in,
                              void* d_out, int out_size) {
    const float* t0 = (const float*)d_in[0];
    const float* t1 = (const float*)d_in[1];
    const float* t2 = (const float*)d_in[2];
    float* out = (float*)d_out;

    KA_reduce<<<9728, 256>>>(t0, t1, t2);
    k4_messages<<<256, 256>>>();
    KB_outputs<<<65536, 256>>>(t0, t1, t2, out);
}

// round 17
// speedup vs baseline: 1.0378x; 1.0004x over previous
#include <cuda_runtime.h>

// Shapes
// theta0: (256, 1024, 256)  idx = x0*262144 + j*256 + c
// theta1: (256, 256, 512)   idx = a*131072 + c*512 + j
// theta2: (256, 256, 512)   idx = c*131072 + b*512 + k
#define N0  67108864
#define N1  33554432
#define N2  33554432

// Scratch (device globals; fully rewritten every call -> deterministic)
__device__ float d_s0a[1024 * 256];      // sum over x0 of theta0  [j][c]
__device__ float d_S0p[2 * 256 * 512];   // partial sum over a of theta1 [half][c][j]
__device__ float d_S2[256 * 256];        // sum over j of theta1 [a][c]
__device__ float d_T2s[256 * 256];       // sum over k of theta2 [c][b]
__device__ float d_msg01[256 * 256];     // [a][c]
__device__ float d_msg12[256 * 256];     // [c][b]
__device__ float d_R[256 * 256];         // [c][b]  (msg21[c,j] = R[c, j>>1])
__device__ float d_Q[256 * 256];         // [a][c]  (msg10[j,c] = Q[j>>2, c])

// 256-bit evict_last load (sm_103a requires .v8.b32/.v4.b64 for this hint).
// Protects t2 lines in L2 across the KA->KB boundary (proven +22us in R10).
__device__ __forceinline__ void ldg_evict_last_8(const float* p, float* f) {
    unsigned long long a, b, c, d;
    asm volatile("ld.global.L2::evict_last.v4.b64 {%0,%1,%2,%3}, [%4];"
                 : "=l"(a), "=l"(b), "=l"(c), "=l"(d) : "l"(p));
    *(unsigned long long*)&f[0] = a;
    *(unsigned long long*)&f[2] = b;
    *(unsigned long long*)&f[4] = c;
    *(unsigned long long*)&f[6] = d;
}

// ---------------------------------------------------------------------------
// KA: fused reductions (exact R10 config). Block roles by blockIdx:
//   [0, 1024)     : k1  s0a[j][c] = sum_x0 theta0[x0,j,c]   (.cs reads)
//   [1024, 1536)  : k2  dual reduction of theta1            (.cs float4 reads)
//   [1536, 9728)  : k3  T2s row sums of theta2              (evict_LAST reads)
__global__ void KA_reduce(const float* __restrict__ t0,
                          const float* __restrict__ t1,
                          const float* __restrict__ t2) {
    const unsigned bb = blockIdx.x;

    if (bb < 1024u) {
        // ---- k1 ----
        const int j = bb;
        const int c = threadIdx.x;
        const float* p = t0 + j * 256 + c;
        float a0 = 0.f, a1 = 0.f, a2 = 0.f, a3 = 0.f;
        float a4 = 0.f, a5 = 0.f, a6 = 0.f, a7 = 0.f;
        #pragma unroll 2
        for (int x = 0; x < 256; x += 8) {
            a0 += __ldcs(p + (size_t)(x + 0) * 262144);
            a1 += __ldcs(p + (size_t)(x + 1) * 262144);
            a2 += __ldcs(p + (size_t)(x + 2) * 262144);
            a3 += __ldcs(p + (size_t)(x + 3) * 262144);
            a4 += __ldcs(p + (size_t)(x + 4) * 262144);
            a5 += __ldcs(p + (size_t)(x + 5) * 262144);
            a6 += __ldcs(p + (size_t)(x + 6) * 262144);
            a7 += __ldcs(p + (size_t)(x + 7) * 262144);
        }
        d_s0a[j * 256 + c] = ((a0 + a1) + (a2 + a3)) + ((a4 + a5) + (a6 + a7));
        return;
    }

    if (bb < 1536u) {
        // ---- k2: dual reduction of theta1 ----
        const unsigned b2 = bb - 1024u;
        const int c    = b2 >> 1;
        const int half = b2 & 1;
        const int tid  = threadIdx.x;
        const int wid  = tid >> 5;
        const int lane = tid & 31;

        __shared__ float4 sS0[8][128];

        float acc[16];
        #pragma unroll
        for (int i = 0; i < 16; i++) acc[i] = 0.f;

        #pragma unroll 2
        for (int it = 0; it < 16; it++) {
            const int a = half * 128 + wid * 16 + it;
            const float4* row = (const float4*)(t1 + (size_t)a * 131072 + (size_t)c * 512);
            float rs = 0.f;
            #pragma unroll
            for (int ch = 0; ch < 4; ch++) {
                float4 v = __ldcs(row + ch * 32 + lane);
                acc[ch * 4 + 0] += v.x;
                acc[ch * 4 + 1] += v.y;
                acc[ch * 4 + 2] += v.z;
                acc[ch * 4 + 3] += v.w;
                rs += (v.x + v.y) + (v.z + v.w);
            }
            #pragma unroll
            for (int off = 16; off > 0; off >>= 1)
                rs += __shfl_down_sync(0xffffffffu, rs, off);
            if (lane == 0) d_S2[a * 256 + c] = rs;
        }

        #pragma unroll
        for (int ch = 0; ch < 4; ch++)
            sS0[wid][ch * 32 + lane] = make_float4(acc[ch * 4 + 0], acc[ch * 4 + 1],
                                                   acc[ch * 4 + 2], acc[ch * 4 + 3]);
        __syncthreads();

        const float* sp = (const float*)sS0;
        float s0 = 0.f, s1 = 0.f;
        #pragma unroll
        for (int w = 0; w < 8; w++) {
            s0 += sp[w * 512 + tid];
            s1 += sp[w * 512 + tid + 256];
        }
        d_S0p[half * 131072 + c * 512 + tid]       = s0;
        d_S0p[half * 131072 + c * 512 + tid + 256] = s1;
        return;
    }

    // ---- k3: T2s[r] = sum_k theta2 row r (evict_last -> stays in L2 for KB) ----
    const int r    = (bb - 1536u) * 8 + (threadIdx.x >> 5);
    const int lane = threadIdx.x & 31;
    const float* row = t2 + (size_t)r * 512;
    float f[8];
    float s = 0.f;
    #pragma unroll
    for (int ch = 0; ch < 2; ch++) {
        ldg_evict_last_8(row + (ch * 32 + lane) * 8, f);
        s += ((f[0] + f[1]) + (f[2] + f[3])) + ((f[4] + f[5]) + (f[6] + f[7]));
    }
    #pragma unroll
    for (int off = 16; off > 0; off >>= 1)
        s += __shfl_down_sync(0xffffffffu, s, off);
    if (lane == 0) d_T2s[r] = s;
}

// ---------------------------------------------------------------------------
// K4: tiny message algebra (exact R10). grid = 256 (c), block = 256.
__global__ void k4_messages() {
    const int c    = blockIdx.x;
    const int t    = threadIdx.x;
    const int lane = t & 31;
    const int wid  = t >> 5;
    __shared__ float sw[8];
    __shared__ float sbc;

    const float v0  = d_s0a[(4 * t + 0) * 256 + c];
    const float v1  = d_s0a[(4 * t + 1) * 256 + c];
    const float v2  = d_s0a[(4 * t + 2) * 256 + c];
    const float v3  = d_s0a[(4 * t + 3) * 256 + c];
    const float2 p0 = *(const float2*)&d_S0p[c * 512 + 2 * t];
    const float2 p1 = *(const float2*)&d_S0p[131072 + c * 512 + 2 * t];
    const float t2s = d_T2s[c * 256 + t];
    const float s2  = d_S2[t * 256 + c];

    const float m01 = (v0 + v1) + (v2 + v3);
    d_msg01[t * 256 + c] = m01;

    float r = m01;
    #pragma unroll
    for (int o = 16; o > 0; o >>= 1) r += __shfl_down_sync(0xffffffffu, r, o);
    if (lane == 0) sw[wid] = r;
    __syncthreads();
    if (t == 0) {
        float s = 0.f;
        #pragma unroll
        for (int w = 0; w < 8; w++) s += sw[w];
        sbc = s;
    }
    __syncthreads();
    const float colsum = sbc;

    const float m12 = (p0.x + p1.x + colsum) + (p0.y + p1.y + colsum);
    d_msg12[c * 256 + t] = m12;

    const float Rv = t2s + 511.f * m12;
    d_R[c * 256 + t] = Rv;

    r = Rv;
    #pragma unroll
    for (int o = 16; o > 0; o >>= 1) r += __shfl_down_sync(0xffffffffu, r, o);
    __syncthreads();
    if (lane == 0) sw[wid] = r;
    __syncthreads();
    if (t == 0) {
        float s = 0.f;
        #pragma unroll
        for (int w = 0; w < 8; w++) s += sw[w];
        sbc = 2.f * s;
    }
    __syncthreads();

    d_Q[t * 256 + c] = s2 + 511.f * m01 + sbc;
}

// ---------------------------------------------------------------------------
// KB: fused broadcast-add outputs. ONLY delta vs R10: 2 independent float4
// per thread (MLP 2, both .cs loads issued before stores), 65536 blocks.
//   [0, 16384)      : theta2 + msg12[c,b]   -- FIRST, reverse order (L2 carry)
//   [16384, 32768)  : theta1 + msg01[a,c] + R[c, j>>1]
//   [32768, 65536)  : theta0 + Q[j>>2, c]
__global__ void KB_outputs(const float* __restrict__ t0,
                           const float* __restrict__ t1,
                           const float* __restrict__ t2,
                           float* __restrict__ out) {
    const unsigned bb = blockIdx.x;

    if (bb < 16384u) {
        // reverse order: read t2 tail first (freshest L2-resident lines)
        const int base4 = (16383 - (int)bb) * 512 + threadIdx.x;
        const int ia = base4;            // float4 index
        const int ib = base4 + 256;
        float4 va = __ldcs((const float4*)t2 + ia);
        float4 vb = __ldcs((const float4*)t2 + ib);
        const float ma = d_msg12[ia >> 7];      // r = (ia*4)>>9
        const float mb = d_msg12[ib >> 7];
        va.x += ma; va.y += ma; va.z += ma; va.w += ma;
        vb.x += mb; vb.y += mb; vb.z += mb; vb.w += mb;
        __stcs((float4*)(out + N0 + N1) + ia, va);
        __stcs((float4*)(out + N0 + N1) + ib, vb);
        return;
    }

    if (bb < 32768u) {
        const int base4 = ((int)bb - 16384) * 512 + threadIdx.x;
        const int ia = base4;
        const int ib = base4 + 256;
        float4 va = __ldcs((const float4*)t1 + ia);
        float4 vb = __ldcs((const float4*)t1 + ib);
        const int ea = ia << 2, eb = ib << 2;
        const int ja = ea & 511,            jb = eb & 511;
        const int ca = (ea >> 9) & 255,     cb = (eb >> 9) & 255;
        const int aa = ea >> 17,            ab = eb >> 17;
        const float m_a = d_msg01[aa * 256 + ca];
        const float m_b = d_msg01[ab * 256 + cb];
        const float2 ra = *(const float2*)&d_R[ca * 256 + (ja >> 1)];
        const float2 rb = *(const float2*)&d_R[cb * 256 + (jb >> 1)];
        va.x += m_a + ra.x; va.y += m_a + ra.x;
        va.z += m_a + ra.y; va.w += m_a + ra.y;
        vb.x += m_b + rb.x; vb.y += m_b + rb.x;
        vb.z += m_b + rb.y; vb.w += m_b + rb.y;
        __stcs((float4*)(out + N0) + ia, va);
        __stcs((float4*)(out + N0) + ib, vb);
        return;
    }

    {
        const int base4 = ((int)bb - 32768) * 512 + threadIdx.x;
        const int ia = base4;
        const int ib = base4 + 256;
        float4 va = __ldcs((const float4*)t0 + ia);
        float4 vb = __ldcs((const float4*)t0 + ib);
        const int ea = ia << 2, eb = ib << 2;
        const int ca = ea & 255,            cb = eb & 255;
        const int jpa = (ea >> 8) & 1023,   jpb = (eb >> 8) & 1023;
        float4 qa = ((const float4*)d_Q)[((jpa >> 2) << 6) + (ca >> 2)];
        float4 qb = ((const float4*)d_Q)[((jpb >> 2) << 6) + (cb >> 2)];
        va.x += qa.x; va.y += qa.y; va.z += qa.z; va.w += qa.w;
        vb.x += qb.x; vb.y += qb.y; vb.z += qb.z; vb.w += qb.w;
        __stcs((float4*)out + ia, va);
        __stcs((float4*)out + ib, vb);
    }
}

// ---------------------------------------------------------------------------
extern "C" void kernel_launch(void* const* d_in, const int* in_sizes, int n_in,
                              void* d_out, int out_size) {
    const float* t0 = (const float*)d_in[0];
    const float* t1 = (const float*)d_in[1];
    const float* t2 = (const float*)d_in[2];
    float* out = (float*)d_out;

    KA_reduce<<<9728, 256>>>(t0, t1, t2);
    k4_messages<<<256, 256>>>();
    KB_outputs<<<65536, 256>>>(t0, t1, t2, out);
}